// round 5
// baseline (speedup 1.0000x reference)
#include <cuda_runtime.h>
#include <math.h>

#define Bsz 256
#define Tt  500
#define Ii  128
#define Hh  512
#define CLIPV 5.0f

#define NBLK 128        // 32 m-tiles x 4 batch-tiles, 1 block/SM
#define NTHR 512        // 2 K-halves x 256 threads -> 4 warps/SMSP
#define MT   16         // m columns per block (x3 gates)
#define BT   64         // batches per block
#define KTOT 640        // 512 (h) + 128 (x)
#define KCH  64
#define NCH  10         // chunks: 0..7 = h, 8..9 = x ; half0: 0..4, half1: 5..9
#define CPH  5          // chunks per half

// smem layout (dynamic):
//  W01: ulonglong2[640][8]  (r,z m-pair packed)        81920 B
//  W2 : ull       [640][8]  (n m-pair packed)          40960 B
//  Hs : float [2 halves][2 bufs][64][66]               67584 B   (also reused for reduction)
#define SM_W01 0
#define SM_W2  81920
#define SM_HS  (81920 + 40960)
#define HS_HALF (2 * KCH * 66 * 4)            // 33792 per half
#define SMEM_BYTES (SM_HS + 2 * HS_HALF)      // 190464

typedef unsigned long long ull;

__device__ float    g_h[2][Bsz * Hh];
__device__ unsigned g_cnt   = 0;
__device__ unsigned g_phase = 0;

__device__ __forceinline__ ull fma2(ull a, ull b, ull c) {
    ull d;
    asm("fma.rn.f32x2 %0, %1, %2, %3;" : "=l"(d) : "l"(a), "l"(b), "l"(c));
    return d;
}
__device__ __forceinline__ ull add2(ull a, ull b) {
    ull d;
    asm("add.rn.f32x2 %0, %1, %2;" : "=l"(d) : "l"(a), "l"(b));
    return d;
}
__device__ __forceinline__ ull pack2(float a, float b) {
    ull d;
    asm("mov.b64 %0, {%1, %2};" : "=l"(d) : "f"(a), "f"(b));
    return d;
}
__device__ __forceinline__ ull dup2(float f) {
    ull d;
    asm("mov.b64 %0, {%1, %1};" : "=l"(d) : "f"(f));
    return d;
}
__device__ __forceinline__ float lo2(ull v) { return __uint_as_float((unsigned)v); }
__device__ __forceinline__ float hi2(ull v) { return __uint_as_float((unsigned)(v >> 32)); }
__device__ __forceinline__ float sigf(float x) { return 1.f / (1.f + __expf(-x)); }

__global__ void __launch_bounds__(NTHR, 1) gru_persist(
    const float* __restrict__ x,      // (B, T, I)
    const float* __restrict__ h0,     // (B, H)
    const float* __restrict__ w_ih,   // (3H, I)
    const float* __restrict__ w_hh,   // (3H, H)
    const float* __restrict__ b_ih,   // (3H)
    const float* __restrict__ b_hh,   // (3H)
    float* __restrict__ out)          // (B, T, H) then (B, H) tail
{
    extern __shared__ char sm[];
    ulonglong2* W01 = (ulonglong2*)(sm + SM_W01);   // [k*8 + tx]
    ull*        W2  = (ull*)(sm + SM_W2);           // [k*8 + tx]

    const int tid   = threadIdx.x;
    const int split = tid >> 8;          // 0 | 1 (K-half)
    const int stid  = tid & 255;
    const int barid = split + 1;

    float* HsB = (float*)(sm + SM_HS + split * HS_HALF);   // [buf][kk][66]
    ull*   red = (ull*)(sm + SM_HS);                       // reduction: [i*256 + stid]

    const int bm  = blockIdx.x & 31;    // 32 m-tiles
    const int bb  = blockIdx.x >> 5;    // 4 batch-tiles
    const int m0  = bm * MT;
    const int b0  = bb * BT;
    const int tx  = stid & 7;           // m-pair lane
    const int TY  = stid >> 3;          // 0..31 -> 2 batches each
    const int m   = m0 + 2 * tx;

    unsigned bar_base = 0;
    if (tid == 0)
        asm volatile("ld.global.cg.u32 %0, [%1];" : "=r"(bar_base) : "l"(&g_phase));

    // ---- one-time: weight slice -> smem, transposed to [k][m-pair] ----
    for (int s = tid; s < KTOT * 8; s += NTHR) {
        const int kk = s >> 3, txx = s & 7, mm = m0 + 2 * txx;
        float wr0, wr1, wz0, wz1, wn0, wn1;
        if (kk < Hh) {
            wr0 = w_hh[(0 * Hh + mm) * Hh + kk]; wr1 = w_hh[(0 * Hh + mm + 1) * Hh + kk];
            wz0 = w_hh[(1 * Hh + mm) * Hh + kk]; wz1 = w_hh[(1 * Hh + mm + 1) * Hh + kk];
            wn0 = w_hh[(2 * Hh + mm) * Hh + kk]; wn1 = w_hh[(2 * Hh + mm + 1) * Hh + kk];
        } else {
            const int kx = kk - Hh;
            wr0 = w_ih[(0 * Hh + mm) * Ii + kx]; wr1 = w_ih[(0 * Hh + mm + 1) * Ii + kx];
            wz0 = w_ih[(1 * Hh + mm) * Ii + kx]; wz1 = w_ih[(1 * Hh + mm + 1) * Ii + kx];
            wn0 = w_ih[(2 * Hh + mm) * Ii + kx]; wn1 = w_ih[(2 * Hh + mm + 1) * Ii + kx];
        }
        W01[kk * 8 + txx] = make_ulonglong2(pack2(wr0, wr1), pack2(wz0, wz1));
        W2[kk * 8 + txx]  = pack2(wn0, wn1);
    }

    const float2 cR  = make_float2(b_ih[m] + b_hh[m],           b_ih[m + 1] + b_hh[m + 1]);
    const float2 cZ  = make_float2(b_ih[Hh + m] + b_hh[Hh + m], b_ih[Hh + m + 1] + b_hh[Hh + m + 1]);
    const float2 cNx = make_float2(b_ih[2 * Hh + m],            b_ih[2 * Hh + m + 1]);
    const float2 cNh = make_float2(b_hh[2 * Hh + m],            b_hh[2 * Hh + m + 1]);

    __syncthreads();

    // staging mapping within a half: row bl, k offsets kq + j*16
    const int bl = stid >> 2;           // 0..63
    const int kq = (stid & 3) * 4;
    const int c0 = split * CPH;         // first chunk of this half

    float4 st_regs[4];

    for (int t = 0; t < Tt; t++) {
        const float* hsrc = (t == 0) ? h0 : g_h[t & 1];
        float*       hdst = g_h[(t + 1) & 1];

        ull aR[2] = {0, 0}, aZ[2] = {0, 0}, aNh[2] = {0, 0}, aNx[2] = {0, 0};

        auto ldg_chunk = [&](int c) {
            const float* p = (c < 8)
                ? hsrc + (size_t)(b0 + bl) * Hh + c * KCH + kq
                : x + ((size_t)(b0 + bl) * Tt + t) * Ii + (c - 8) * KCH + kq;
            #pragma unroll
            for (int j = 0; j < 4; j++)
                st_regs[j] = __ldcg((const float4*)(p + j * 16));
        };
        auto sts_chunk = [&](int buf) {
            float* H = HsB + buf * (KCH * 66);
            #pragma unroll
            for (int j = 0; j < 4; j++) {
                const int kl = kq + j * 16;
                H[(kl + 0) * 66 + bl] = st_regs[j].x;
                H[(kl + 1) * 66 + bl] = st_regs[j].y;
                H[(kl + 2) * 66 + bl] = st_regs[j].z;
                H[(kl + 3) * 66 + bl] = st_regs[j].w;
            }
        };
        auto compute = [&](int buf, int c) {
            const float* H = HsB + buf * (KCH * 66);
            const int kc = c * KCH;
            const bool hphase = (c < 8);
            #pragma unroll 16
            for (int kk = 0; kk < KCH; kk++) {
                ulonglong2 w01 = W01[(kc + kk) * 8 + tx];
                ull        w2v = W2[(kc + kk) * 8 + tx];
                float2 h2 = *(const float2*)(H + kk * 66 + 2 * TY);
                ull d0 = dup2(h2.x), d1 = dup2(h2.y);
                aR[0] = fma2(d0, w01.x, aR[0]);  aR[1] = fma2(d1, w01.x, aR[1]);
                aZ[0] = fma2(d0, w01.y, aZ[0]);  aZ[1] = fma2(d1, w01.y, aZ[1]);
                if (hphase) { aNh[0] = fma2(d0, w2v, aNh[0]); aNh[1] = fma2(d1, w2v, aNh[1]); }
                else        { aNx[0] = fma2(d0, w2v, aNx[0]); aNx[1] = fma2(d1, w2v, aNx[1]); }
            }
        };

        // per-half double-buffered chunk pipeline (named barrier = this half only)
        ldg_chunk(c0);
        sts_chunk(0);
        ldg_chunk(c0 + 1);
        asm volatile("bar.sync %0, 256;" :: "r"(barid) : "memory");
        #pragma unroll
        for (int i = 0; i < CPH; i++) {
            const int buf = i & 1;
            if (i + 1 < CPH) sts_chunk((i + 1) & 1);
            if (i + 2 < CPH) ldg_chunk(c0 + i + 2);
            compute(buf, c0 + i);
            asm volatile("bar.sync %0, 256;" :: "r"(barid) : "memory");
        }

        // ---- cross-half reduction (SoA layout, conflict-free) ----
        __syncthreads();
        if (split == 1) {
            red[0 * 256 + stid] = aR[0];  red[1 * 256 + stid] = aR[1];
            red[2 * 256 + stid] = aZ[0];  red[3 * 256 + stid] = aZ[1];
            red[4 * 256 + stid] = aNh[0]; red[5 * 256 + stid] = aNh[1];
            red[6 * 256 + stid] = aNx[0]; red[7 * 256 + stid] = aNx[1];
        }
        __syncthreads();

        if (split == 0) {
            aR[0]  = add2(aR[0],  red[0 * 256 + stid]);
            aR[1]  = add2(aR[1],  red[1 * 256 + stid]);
            aZ[0]  = add2(aZ[0],  red[2 * 256 + stid]);
            aZ[1]  = add2(aZ[1],  red[3 * 256 + stid]);
            aNh[0] = add2(aNh[0], red[4 * 256 + stid]);
            aNh[1] = add2(aNh[1], red[5 * 256 + stid]);
            aNx[0] = add2(aNx[0], red[6 * 256 + stid]);
            aNx[1] = add2(aNx[1], red[7 * 256 + stid]);

            // ---- gates epilogue ----
            #pragma unroll
            for (int i2 = 0; i2 < 2; i2++) {
                const int b = b0 + 2 * TY + i2;
                float2 hp = __ldcg((const float2*)(hsrc + (size_t)b * Hh + m));

                float rl = sigf(lo2(aR[i2]) + cR.x);
                float rh = sigf(hi2(aR[i2]) + cR.y);
                float zl = sigf(lo2(aZ[i2]) + cZ.x);
                float zh = sigf(hi2(aZ[i2]) + cZ.y);
                float nl = tanhf(lo2(aNx[i2]) + cNx.x + rl * (lo2(aNh[i2]) + cNh.x));
                float nh = tanhf(hi2(aNx[i2]) + cNx.y + rh * (hi2(aNh[i2]) + cNh.y));

                float hl  = (1.f - zl) * nl + zl * hp.x;
                float hhv = (1.f - zh) * nh + zh * hp.y;
                hl  = fminf(fmaxf(hl,  -CLIPV), CLIPV);
                hhv = fminf(fmaxf(hhv, -CLIPV), CLIPV);

                float2 res = make_float2(hl, hhv);
                __stcg((float2*)(hdst + (size_t)b * Hh + m), res);
                *(float2*)(out + ((size_t)b * Tt + t) * Hh + m) = res;
                if (t == Tt - 1)
                    *(float2*)(out + (size_t)Bsz * Tt * Hh + (size_t)b * Hh + m) = res;
            }
        }

        // ---- grid barrier (monotonic phase, wrap-safe) ----
        __syncthreads();
        if (tid == 0) {
            __threadfence();
            unsigned old = atomicAdd(&g_cnt, 1u);
            if (old == (unsigned)(NBLK - 1)) {
                atomicExch(&g_cnt, 0u);
                __threadfence();
                atomicAdd(&g_phase, 1u);
            } else {
                const unsigned tgt = bar_base + (unsigned)(t + 1);
                unsigned v;
                do {
                    __nanosleep(32);
                    asm volatile("ld.global.cg.u32 %0, [%1];" : "=r"(v) : "l"(&g_phase));
                } while ((int)(v - tgt) < 0);
            }
            __threadfence();
        }
        __syncthreads();
    }
}

extern "C" void kernel_launch(void* const* d_in, const int* in_sizes, int n_in,
                              void* d_out, int out_size)
{
    (void)in_sizes; (void)n_in; (void)out_size;
    const float* x    = (const float*)d_in[0];
    const float* h0   = (const float*)d_in[1];
    const float* w_ih = (const float*)d_in[2];
    const float* w_hh = (const float*)d_in[3];
    const float* b_ih = (const float*)d_in[4];
    const float* b_hh = (const float*)d_in[5];
    float* out = (float*)d_out;

    cudaFuncSetAttribute(gru_persist, cudaFuncAttributeMaxDynamicSharedMemorySize,
                         SMEM_BYTES);

    gru_persist<<<NBLK, NTHR, SMEM_BYTES>>>(x, h0, w_ih, w_hh, b_ih, b_hh, out);
}